// round 9
// baseline (speedup 1.0000x reference)
#include <cuda_runtime.h>
#include <math.h>

#define T_LEN    4096
#define NTHREADS 256
#define CHUNK    16              // contiguous timesteps per thread
#define NWARPS   (NTHREADS / 32)
#define FULL     0xFFFFFFFFu

__global__ __launch_bounds__(NTHREADS, 6)
void garch_kernel(const float4* __restrict__ x4,
                  const float* __restrict__ omega_log,
                  const float* __restrict__ alpha_log,
                  const float* __restrict__ beta_log,
                  float4* __restrict__ out4)
{
    __shared__ float Aw[NWARPS], Bw[NWARPS];
    __shared__ float sumw[NWARPS], sqw[NWARPS];
    __shared__ float s0_sh;

    const int tid  = threadIdx.x;
    const int lane = tid & 31;
    const int wid  = tid >> 5;

    // ---- scalar params ----
    const float ea    = expf(alpha_log[0]);
    const float eb    = expf(beta_log[0]);
    const float denom = 1.0f + ea + eb;
    const float omega = expf(omega_log[0]);
    const float alpha = ea / denom;
    const float beta  = eb / denom;
    const float bb2 = beta * beta, bb4 = bb2 * bb2, bb8 = bb4 * bb4;
    const float beta16 = bb8 * bb8;       // per-thread A, invariant

    // ---- load 16 contiguous elements (4 x LDG.128, 64B lane stride) ----
    // per warp instruction: 32 distinct 32B sectors = same L1/DRAM cost as coalesced
    const size_t row4 = (size_t)blockIdx.x * (T_LEN / 4);
    const float4* xr = x4 + row4 + 4 * (size_t)tid;
    float4 v0 = __ldcs(xr + 0);
    float4 v1 = __ldcs(xr + 1);
    float4 v2 = __ldcs(xr + 2);
    float4 v3 = __ldcs(xr + 3);

    // ---- variance partials + precompute c_t = alpha*x_t^2 + omega ----
    float c[CHUNK];
    float sum = 0.0f, sq = 0.0f;
    {
        const float xs[CHUNK] = { v0.x, v0.y, v0.z, v0.w,
                                  v1.x, v1.y, v1.z, v1.w,
                                  v2.x, v2.y, v2.z, v2.w,
                                  v3.x, v3.y, v3.z, v3.w };
        #pragma unroll
        for (int j = 0; j < CHUNK; j++) {
            float x2 = xs[j] * xs[j];
            sum += xs[j];
            sq  += x2;
            c[j] = fmaf(alpha, x2, omega);
        }
    }
    #pragma unroll
    for (int off = 16; off > 0; off >>= 1) {
        sum += __shfl_xor_sync(FULL, sum, off);
        sq  += __shfl_xor_sync(FULL, sq,  off);
    }
    if (lane == 0) { sumw[wid] = sum; sqw[wid] = sq; }

    // ---- local affine over 16 contiguous steps: s -> A*s + B ----
    float B = c[0];
    #pragma unroll
    for (int j = 1; j < CHUNK; j++)
        B = fmaf(beta, B, c[j]);
    float A = beta16;

    // ---- single warp inclusive scan of (A, B) ----
    #pragma unroll
    for (int off = 1; off < 32; off <<= 1) {
        float au = __shfl_up_sync(FULL, A, off);
        float bu = __shfl_up_sync(FULL, B, off);
        if (lane >= off) {
            B = fmaf(A, bu, B);
            A *= au;
        }
    }
    if (lane == 31) { Aw[wid] = A; Bw[wid] = B; }
    __syncthreads();

    // ---- warp 0: scan the 8 warp aggregates; warp 1: finish variance ----
    if (wid == 0) {
        float a = (lane < NWARPS) ? Aw[lane] : 1.0f;
        float b = (lane < NWARPS) ? Bw[lane] : 0.0f;
        #pragma unroll
        for (int off = 1; off < NWARPS; off <<= 1) {
            float au = __shfl_up_sync(FULL, a, off);
            float bu = __shfl_up_sync(FULL, b, off);
            if (lane >= off) { b = fmaf(a, bu, b); a *= au; }
        }
        if (lane < NWARPS) { Aw[lane] = a; Bw[lane] = b; }
    }
    if (wid == 1) {
        float ts = (lane < NWARPS) ? sumw[lane] : 0.0f;
        float tq = (lane < NWARPS) ? sqw[lane]  : 0.0f;
        #pragma unroll
        for (int off = 4; off > 0; off >>= 1) {
            ts += __shfl_xor_sync(FULL, ts, off);
            tq += __shfl_xor_sync(FULL, tq, off);
        }
        if (lane == 0) {
            s0_sh = (tq - ts * ts * (1.0f / (float)T_LEN))
                    * (1.0f / (float)(T_LEN - 1));
        }
    }
    __syncthreads();
    const float s0 = s0_sh;

    // ---- exclusive prefix for this thread, applied to s0 ----
    float a_exc = __shfl_up_sync(FULL, A, 1);
    float b_exc = __shfl_up_sync(FULL, B, 1);
    if (lane == 0) { a_exc = 1.0f; b_exc = 0.0f; }
    float a_wp = 1.0f, b_wp = 0.0f;
    if (wid > 0) { a_wp = Aw[wid - 1]; b_wp = Bw[wid - 1]; }
    // s at step 16*tid: thread-exclusive (later) ∘ warp-prefix (earlier) on s0
    float s = fmaf(a_exc * a_wp, s0, fmaf(a_exc, b_wp, b_exc));

    // ---- replay 16 steps; outputs shifted by one: {sqrt(s_in), sqrt(s1), ...} ----
    float4* orow = out4 + row4 + 4 * (size_t)tid;
    float4 o;
    o.x = s * rsqrtf(s); s = fmaf(beta, s, c[0]);
    o.y = s * rsqrtf(s); s = fmaf(beta, s, c[1]);
    o.z = s * rsqrtf(s); s = fmaf(beta, s, c[2]);
    o.w = s * rsqrtf(s); s = fmaf(beta, s, c[3]);
    __stcs(orow + 0, o);
    o.x = s * rsqrtf(s); s = fmaf(beta, s, c[4]);
    o.y = s * rsqrtf(s); s = fmaf(beta, s, c[5]);
    o.z = s * rsqrtf(s); s = fmaf(beta, s, c[6]);
    o.w = s * rsqrtf(s); s = fmaf(beta, s, c[7]);
    __stcs(orow + 1, o);
    o.x = s * rsqrtf(s); s = fmaf(beta, s, c[8]);
    o.y = s * rsqrtf(s); s = fmaf(beta, s, c[9]);
    o.z = s * rsqrtf(s); s = fmaf(beta, s, c[10]);
    o.w = s * rsqrtf(s); s = fmaf(beta, s, c[11]);
    __stcs(orow + 2, o);
    o.x = s * rsqrtf(s); s = fmaf(beta, s, c[12]);
    o.y = s * rsqrtf(s); s = fmaf(beta, s, c[13]);
    o.z = s * rsqrtf(s); s = fmaf(beta, s, c[14]);
    o.w = s * rsqrtf(s);                              // final state discarded
    __stcs(orow + 3, o);
}

extern "C" void kernel_launch(void* const* d_in, const int* in_sizes, int n_in,
                              void* d_out, int out_size)
{
    const float4* x4       = (const float4*)d_in[0];
    const float* omega_log = (const float*)d_in[1];
    const float* alpha_log = (const float*)d_in[2];
    const float* beta_log  = (const float*)d_in[3];
    float4* out4 = (float4*)d_out;

    const int B = in_sizes[0] / T_LEN;   // 4096 rows
    garch_kernel<<<B, NTHREADS>>>(x4, omega_log, alpha_log, beta_log, out4);
}

// round 12
// speedup vs baseline: 1.2452x; 1.2452x over previous
#include <cuda_runtime.h>
#include <math.h>

#define T_LEN    4096
#define NTHREADS 256
#define NSEG     4               // segments of 1024 elements
#define NWARPS   (NTHREADS / 32)
#define FULL     0xFFFFFFFFu

__global__ __launch_bounds__(NTHREADS, 5)
void garch_kernel(const float4* __restrict__ x4,
                  const float* __restrict__ omega_log,
                  const float* __restrict__ alpha_log,
                  const float* __restrict__ beta_log,
                  float4* __restrict__ out4)
{
    __shared__ float BwS[NSEG][NWARPS];   // per-segment cross-warp B scan
    __shared__ float sumw[NWARPS], sqw[NWARPS];
    __shared__ float s0_sh;

    const int tid  = threadIdx.x;
    const int lane = tid & 31;
    const int wid  = tid >> 5;

    // ---- scalar params ----
    const float ea    = expf(alpha_log[0]);
    const float eb    = expf(beta_log[0]);
    const float denom = 1.0f + ea + eb;
    const float omega = expf(omega_log[0]);
    const float alpha = ea / denom;
    const float beta  = eb / denom;

    // powers of beta by repeated squaring: m[i] = beta^(4*2^i)
    float m0 = beta * beta;  m0 = m0 * m0;      // beta^4
    const float m1 = m0 * m0;                   // beta^8
    const float m2 = m1 * m1;                   // beta^16
    const float m3 = m2 * m2;                   // beta^32
    const float m4 = m3 * m3;                   // beta^64
    const float p128_1 = m4 * m4;               // beta^128
    const float p128_2 = p128_1 * p128_1;       // beta^256
    const float p128_4 = p128_2 * p128_2;       // beta^512
    const float beta1024 = p128_4 * p128_4;     // beta^1024 (segment A)

    // ---- load: 4 coalesced float4 per thread (the float4 IS the chunk) ----
    const size_t row4 = (size_t)blockIdx.x * (NSEG * NTHREADS);
    float4 v[NSEG];
    #pragma unroll
    for (int j = 0; j < NSEG; j++)
        v[j] = __ldcs(&x4[row4 + j * NTHREADS + tid]);

    // ---- variance partials + c_t = alpha*x_t^2 + omega ----
    float c[NSEG][4];
    float sum = 0.0f, sq = 0.0f;
    #pragma unroll
    for (int j = 0; j < NSEG; j++) {
        float xs[4] = { v[j].x, v[j].y, v[j].z, v[j].w };
        #pragma unroll
        for (int k = 0; k < 4; k++) {
            float x2 = xs[k] * xs[k];
            sum += xs[k];
            sq  += x2;
            c[j][k] = fmaf(alpha, x2, omega);
        }
    }
    #pragma unroll
    for (int off = 16; off > 0; off >>= 1) {
        sum += __shfl_xor_sync(FULL, sum, off);
        sq  += __shfl_xor_sync(FULL, sq,  off);
    }
    if (lane == 0) { sumw[wid] = sum; sqw[wid] = sq; }

    // ---- per-segment local B over 4 steps (A = beta^4, constant) ----
    float B[NSEG];
    #pragma unroll
    for (int j = 0; j < NSEG; j++) {
        float b = c[j][0];
        b = fmaf(beta, b, c[j][1]);
        b = fmaf(beta, b, c[j][2]);
        b = fmaf(beta, b, c[j][3]);
        B[j] = b;
    }

    // ---- B-only warp scans, constant multiplier per step: beta^(4*off) ----
    {
        const float mult[5] = { m0, m1, m2, m3, m4 };
        #pragma unroll
        for (int i = 0; i < 5; i++) {
            const int off = 1 << i;
            float bu[NSEG];
            #pragma unroll
            for (int j = 0; j < NSEG; j++)
                bu[j] = __shfl_up_sync(FULL, B[j], off);
            if (lane >= off) {
                #pragma unroll
                for (int j = 0; j < NSEG; j++)
                    B[j] = fmaf(mult[i], bu[j], B[j]);
            }
        }
    }
    if (lane == 31) {
        #pragma unroll
        for (int j = 0; j < NSEG; j++) BwS[j][wid] = B[j];
    }
    __syncthreads();

    // ---- warp 0: four 8-element cross-warp B scans (multiplier beta^(128*off)) ----
    if (wid == 0) {
        const int g  = lane >> 3;
        const int l8 = lane & 7;
        float b = BwS[g][l8];
        float bu;
        bu = __shfl_up_sync(FULL, b, 1); if (l8 >= 1) b = fmaf(p128_1, bu, b);
        bu = __shfl_up_sync(FULL, b, 2); if (l8 >= 2) b = fmaf(p128_2, bu, b);
        bu = __shfl_up_sync(FULL, b, 4); if (l8 >= 4) b = fmaf(p128_4, bu, b);
        BwS[g][l8] = b;
    }
    // ---- warp 1: finish variance concurrently ----
    if (wid == 1) {
        float ts = (lane < NWARPS) ? sumw[lane] : 0.0f;
        float tq = (lane < NWARPS) ? sqw[lane]  : 0.0f;
        #pragma unroll
        for (int off = 4; off > 0; off >>= 1) {
            ts += __shfl_xor_sync(FULL, ts, off);
            tq += __shfl_xor_sync(FULL, tq, off);
        }
        if (lane == 0) {
            s0_sh = (tq - ts * ts * (1.0f / (float)T_LEN))
                    * (1.0f / (float)(T_LEN - 1));
        }
    }
    __syncthreads();
    const float s0 = s0_sh;

    // ---- segment base states: S_{j+1} = beta^1024 * S_j + Bfull_j ----
    float S[NSEG];
    S[0] = s0;
    #pragma unroll
    for (int j = 0; j < NSEG - 1; j++)
        S[j + 1] = fmaf(beta1024, S[j], BwS[j][NWARPS - 1]);

    // ---- exclusive prefixes: b via shuffle, a from lane/wid bits (no shuffle) ----
    float b_exc[NSEG];
    #pragma unroll
    for (int j = 0; j < NSEG; j++) {
        b_exc[j] = __shfl_up_sync(FULL, B[j], 1);
        if (lane == 0) b_exc[j] = 0.0f;
    }
    float a_exc = 1.0f;                         // beta^(4*lane)
    if (lane & 1)  a_exc *= m0;
    if (lane & 2)  a_exc *= m1;
    if (lane & 4)  a_exc *= m2;
    if (lane & 8)  a_exc *= m3;
    if (lane & 16) a_exc *= m4;
    float a_wp = 1.0f;                          // beta^(128*wid)
    if (wid & 1) a_wp *= p128_1;
    if (wid & 2) a_wp *= p128_2;
    if (wid & 4) a_wp *= p128_4;
    const float a_tot = a_exc * a_wp;

    // ---- replay all 4 segments (independent chains -> MUFU/FMA ILP) ----
    #pragma unroll
    for (int j = 0; j < NSEG; j++) {
        float b_wp = (wid > 0) ? BwS[j][wid - 1] : 0.0f;
        float s = fmaf(a_tot, S[j], fmaf(a_exc, b_wp, b_exc[j]));

        float4 o;
        o.x = s * rsqrtf(s); s = fmaf(beta, s, c[j][0]);
        o.y = s * rsqrtf(s); s = fmaf(beta, s, c[j][1]);
        o.z = s * rsqrtf(s); s = fmaf(beta, s, c[j][2]);
        o.w = s * rsqrtf(s);

        __stcs(&out4[row4 + j * NTHREADS + tid], o);
    }
}

extern "C" void kernel_launch(void* const* d_in, const int* in_sizes, int n_in,
                              void* d_out, int out_size)
{
    const float4* x4       = (const float4*)d_in[0];
    const float* omega_log = (const float*)d_in[1];
    const float* alpha_log = (const float*)d_in[2];
    const float* beta_log  = (const float*)d_in[3];
    float4* out4 = (float4*)d_out;

    const int B = in_sizes[0] / T_LEN;   // 4096 rows
    garch_kernel<<<B, NTHREADS>>>(x4, omega_log, alpha_log, beta_log, out4);
}